// round 16
// baseline (speedup 1.0000x reference)
#include <cuda_runtime.h>
#include <cuda_fp16.h>
#include <cstdint>

#define B_    1024
#define T_    256
#define D_    64
#define H_    128
#define GC    384

__device__ __half g_xproj[(size_t)B_ * T_ * GC];   // fp16 x-projections (~201MB)
__device__ int    g_order[B_];
__device__ uint2  g_bfx[6144];    // Phase-A W fragments (fp16), [48nt][4ks][32ln]

__device__ __forceinline__ float sigmoidf_(float x) {
    return __fdividef(1.0f, 1.0f + __expf(-x));
}
__device__ __forceinline__ float tanhf_(float x) {
    return 1.0f - __fdividef(2.0f, __expf(2.0f * x) + 1.0f);
}

// ---------------- warp-level fp16 MMA (f32 accum) ----------------
__device__ __forceinline__ void mma16816(float* d, const uint32_t* a, uint32_t b0, uint32_t b1) {
    asm volatile(
        "mma.sync.aligned.m16n8k16.row.col.f32.f16.f16.f32 "
        "{%0,%1,%2,%3}, {%4,%5,%6,%7}, {%8,%9}, {%0,%1,%2,%3};"
        : "+f"(d[0]), "+f"(d[1]), "+f"(d[2]), "+f"(d[3])
        : "r"(a[0]), "r"(a[1]), "r"(a[2]), "r"(a[3]), "r"(b0), "r"(b1));
}

__device__ __forceinline__ uint32_t pack_h2(float x, float y) {
    __half2 h = __floats2half2_rn(x, y);
    return *reinterpret_cast<uint32_t*>(&h);
}
__device__ __forceinline__ uint32_t split_pack_h(float x, float y, uint32_t& lo) {
    __half hx = __float2half_rn(x), hy = __float2half_rn(y);
    float rx = x - __half2float(hx), ry = y - __half2float(hy);
    __half2 hp = __halves2half2(hx, hy);
    __half2 lp = __floats2half2_rn(rx, ry);
    lo = *reinterpret_cast<uint32_t*>(&lp);
    return *reinterpret_cast<uint32_t*>(&hp);
}

// B-fragment builder (fp16) for RECURRENT W rows (64+k)
__device__ __forceinline__ uint2 frag_make(const float* W, int ldn, int nt, int ks, int ln) {
    int g = ln >> 2, tg = ln & 3;
    int n = 8 * nt + g, k0 = 16 * ks + 2 * tg;
    uint32_t h0 = pack_h2(W[(64 + k0)     * ldn + n], W[(64 + k0 + 1) * ldn + n]);
    uint32_t h1 = pack_h2(W[(64 + k0 + 8) * ldn + n], W[(64 + k0 + 9) * ldn + n]);
    return make_uint2(h0, h1);
}

// B-fragment builder (fp16) for X-PART W rows (0..63)
__device__ __forceinline__ uint2 frag_make_x(const float* gkp, const float* ckp,
                                             int nt, int ks, int ln) {
    int g = ln >> 2, tg = ln & 3;
    int n = 8 * nt + g, k0 = 16 * ks + 2 * tg;
    float w00, w01, w10, w11;
    if (n < 256) {
        w00 = gkp[k0 * 256 + n];       w01 = gkp[(k0 + 1) * 256 + n];
        w10 = gkp[(k0 + 8) * 256 + n]; w11 = gkp[(k0 + 9) * 256 + n];
    } else {
        int m = n - 256;
        w00 = ckp[k0 * 128 + m];       w01 = ckp[(k0 + 1) * 128 + m];
        w10 = ckp[(k0 + 8) * 128 + m]; w11 = ckp[(k0 + 9) * 128 + m];
    }
    return make_uint2(pack_h2(w00, w01), pack_h2(w10, w11));
}

// ---------------- setup: sort (block 0) + Phase-A weight frag build (block 1) ----------
__global__ void setup_kernel(const int* __restrict__ seq_lens,
                             const float* __restrict__ gk, const float* __restrict__ ck) {
    int tid = threadIdx.x;
    if (blockIdx.x == 0) {
        __shared__ int hist[T_];
        __shared__ int offs[T_];
        for (int i = tid; i < T_; i += 256) hist[i] = 0;
        __syncthreads();
        for (int i = tid; i < B_; i += 256) atomicAdd(&hist[T_ - 1 - seq_lens[i]], 1);
        __syncthreads();
        if (tid == 0) { int s = 0; for (int k = 0; k < T_; k++) { offs[k] = s; s += hist[k]; } }
        __syncthreads();
        for (int i = tid; i < T_; i += 256) hist[i] = 0;
        __syncthreads();
        for (int i = tid; i < B_; i += 256) {
            int key = T_ - 1 - seq_lens[i];
            g_order[offs[key] + atomicAdd(&hist[key], 1)] = i;
        }
    } else {
        for (int idx = tid; idx < 6144; idx += 256) {
            int nt = idx >> 7, ks = (idx >> 5) & 3, ln = idx & 31;
            g_bfx[idx] = frag_make_x(gk, ck, nt, ks, ln);
        }
    }
}

// ---------------- Phase A v4: fp16 single pass, per-warp len skip ----------------
static constexpr int BIAS_OFF = 0;        // 384 f32
static constexpr int AH_OFF   = 1536;     // [128][72] fp16
static constexpr int PA_SMEM  = 20096;
#define SA 72

__global__ void __launch_bounds__(256, 4) xproj_mma_kernel(
    const int* __restrict__ item_his, const int* __restrict__ seq_lens,
    const float* __restrict__ emb,
    const float* __restrict__ gb, const float* __restrict__ cb)
{
    extern __shared__ char dynsmem[];
    float*  sBias = (float*)(dynsmem + BIAS_OFF);
    __half* sAh   = (__half*)(dynsmem + AH_OFF);

    int b  = blockIdx.x >> 1;
    int t0 = (blockIdx.x & 1) << 7;
    int len = seq_lens[b];
    if (t0 >= len) return;
    int mrows = len - t0;

    int tid = threadIdx.x;

    for (int i = tid; i < GC; i += 256) sBias[i] = (i < 256) ? gb[i] : cb[i - 256];

    {
        int r = tid >> 1, half = tid & 1;
        int item = item_his[b * T_ + t0 + r];
        const float4* e4 = reinterpret_cast<const float4*>(emb + (size_t)item * D_ + half * 32);
        #pragma unroll
        for (int q = 0; q < 8; q += 2) {
            float4 v0 = e4[q], v1 = e4[q + 1];
            uint32_t p[4];
            p[0] = pack_h2(v0.x, v0.y);
            p[1] = pack_h2(v0.z, v0.w);
            p[2] = pack_h2(v1.x, v1.y);
            p[3] = pack_h2(v1.z, v1.w);
            int c0 = half * 32 + q * 4;
            *reinterpret_cast<uint4*>(&sAh[r * SA + c0]) = *reinterpret_cast<uint4*>(p);
        }
    }
    __syncthreads();

    int wid = tid >> 5, lane = tid & 31;
    int gid = lane >> 2, tig = lane & 3;
    int m0 = wid * 16;

    if (m0 >= mrows) return;

    uint32_t ah[4][4];
    #pragma unroll
    for (int ks = 0; ks < 4; ks++) {
        int c = ks * 16 + 2 * tig;
        ah[ks][0] = *reinterpret_cast<const uint32_t*>(&sAh[(m0+gid)   * SA + c]);
        ah[ks][1] = *reinterpret_cast<const uint32_t*>(&sAh[(m0+gid+8) * SA + c]);
        ah[ks][2] = *reinterpret_cast<const uint32_t*>(&sAh[(m0+gid)   * SA + c + 8]);
        ah[ks][3] = *reinterpret_cast<const uint32_t*>(&sAh[(m0+gid+8) * SA + c + 8]);
    }

    __half* outbase = g_xproj + ((size_t)b * T_ + t0) * GC;
    const uint2* __restrict__ fH = g_bfx;

    for (int nt = 0; nt < 48; nt += 2) {
        float acc0[4] = {0.f, 0.f, 0.f, 0.f};
        float acc1[4] = {0.f, 0.f, 0.f, 0.f};
        #pragma unroll
        for (int ks = 0; ks < 4; ks++) {
            uint2 bh0 = __ldg(&fH[(nt       * 4 + ks) * 32 + lane]);
            uint2 bh1 = __ldg(&fH[((nt + 1) * 4 + ks) * 32 + lane]);
            mma16816(acc0, ah[ks], bh0.x, bh0.y);
            mma16816(acc1, ah[ks], bh1.x, bh1.y);
        }
        #pragma unroll
        for (int p = 0; p < 2; p++) {
            float* acc = p ? acc1 : acc0;
            int ncol = (nt + p) * 8 + 2 * tig;
            float2 bias = *reinterpret_cast<const float2*>(&sBias[ncol]);
            uint32_t o0 = pack_h2(acc[0] + bias.x, acc[1] + bias.y);
            uint32_t o1 = pack_h2(acc[2] + bias.x, acc[3] + bias.y);
            *reinterpret_cast<uint32_t*>(&outbase[(size_t)(m0 + gid)     * GC + ncol]) = o0;
            *reinterpret_cast<uint32_t*>(&outbase[(size_t)(m0 + gid + 8) * GC + ncol]) = o1;
        }
    }
}

// ---------------- Phase B: fp16 GRU, depth-2 MMA chains ----------------
static constexpr int OFF_A    = 0;        // u32[8ks][32ln][4]  4096 B
static constexpr int OFF_R    = 4096;
static constexpr int OFF_H    = 8192;     // f32[8][132]        4224 B
static constexpr int OFF_U    = 12416;
static constexpr int OFF_META = 16640;
static constexpr int G_SMEM   = 16768;
#define HS 132

__global__ void __launch_bounds__(512, 1) gru_mma_kernel(
    const int* __restrict__ seq_lens,
    const float* __restrict__ gk, const float* __restrict__ ck,
    float* __restrict__ out)
{
    extern __shared__ char dynsmem[];
    uint32_t* sA = (uint32_t*)(dynsmem + OFF_A);
    uint32_t* sR = (uint32_t*)(dynsmem + OFF_R);
    float* sH = (float*)(dynsmem + OFF_H);
    float* sU = (float*)(dynsmem + OFF_U);
    int* srow = (int*)(dynsmem + OFF_META);
    int* slen = srow + 8;

    int tid = threadIdx.x;
    int wid = tid >> 5, lane = tid & 31;
    int gid = lane >> 2, tig = lane & 3;
    int nt0 = 2 * wid, nt1 = nt0 + 1;

    uint2 BgH0[8], BgH1[8], BcH[8];
    #pragma unroll
    for (int ks = 0; ks < 8; ks++) {
        BgH0[ks] = frag_make(gk, 256, nt0, ks, lane);
        BgH1[ks] = frag_make(gk, 256, nt1, ks, lane);
        BcH[ks]  = frag_make(ck, 128, wid, ks, lane);
    }
    for (int i = tid; i < 1024; i += 512) { sA[i] = 0u; sR[i] = 0u; }
    for (int i = tid; i < 8 * HS; i += 512) { sH[i] = 0.0f; sU[i] = 0.0f; }
    if (tid < 8) {
        int row = g_order[blockIdx.x * 8 + tid];
        srow[tid] = row;
        slen[tid] = seq_lens[row];
    }
    __syncthreads();

    int maxlen = slen[0];
    int mylen  = slen[gid];
    size_t myxoff = (size_t)srow[gid] * (T_ * GC);
    int cA0 = 16 * wid + 2 * tig;
    int cA1 = cA0 + 8;
    int j0  = 8 * wid + 2 * tig;
    bool isR = (wid < 8);
    int rhOff = (wid * 32 + lane) * 4;
    int ahOff = ((j0 >> 4) * 32 + lane) * 4 + ((wid & 1) ? 2 : 0);

    float2 xg0 = make_float2(0.f, 0.f), xg1 = make_float2(0.f, 0.f), xc = make_float2(0.f, 0.f);
    if (0 < mylen) {
        xg0 = __half22float2(*reinterpret_cast<const __half2*>(&g_xproj[myxoff + cA0]));
        xg1 = __half22float2(*reinterpret_cast<const __half2*>(&g_xproj[myxoff + cA1]));
        xc  = __half22float2(*reinterpret_cast<const __half2*>(&g_xproj[myxoff + 256 + j0]));
    }

    for (int t = 0; t < maxlen; t++) {
        float2 xg0n = make_float2(0.f, 0.f), xg1n = make_float2(0.f, 0.f);
        float2 xcn  = make_float2(0.f, 0.f);
        if (t + 1 < mylen) {
            size_t bn = myxoff + (size_t)(t + 1) * GC;
            xg0n = __half22float2(*reinterpret_cast<const __half2*>(&g_xproj[bn + cA0]));
            xg1n = __half22float2(*reinterpret_cast<const __half2*>(&g_xproj[bn + cA1]));
            xcn  = __half22float2(*reinterpret_cast<const __half2*>(&g_xproj[bn + 256 + j0]));
        }
        bool act = (t < mylen);

        // ---- gate MMA: 8 independent chains of depth 2 (4 per nt) ----
        float g0[4][4], g1[4][4];
        #pragma unroll
        for (int kp = 0; kp < 4; kp++) {
            #pragma unroll
            for (int e = 0; e < 4; e++) { g0[kp][e] = 0.f; g1[kp][e] = 0.f; }
            uint4 aA = *reinterpret_cast<const uint4*>(&sA[((2*kp)   * 32 + lane) * 4]);
            uint4 aB = *reinterpret_cast<const uint4*>(&sA[((2*kp+1) * 32 + lane) * 4]);
            const uint32_t* pA = reinterpret_cast<const uint32_t*>(&aA);
            const uint32_t* pB = reinterpret_cast<const uint32_t*>(&aB);
            mma16816(g0[kp], pA, BgH0[2*kp].x,   BgH0[2*kp].y);
            mma16816(g1[kp], pA, BgH1[2*kp].x,   BgH1[2*kp].y);
            mma16816(g0[kp], pB, BgH0[2*kp+1].x, BgH0[2*kp+1].y);
            mma16816(g1[kp], pB, BgH1[2*kp+1].x, BgH1[2*kp+1].y);
        }
        float e0 = ((g0[0][0]+g0[0][2]) + (g0[1][0]+g0[1][2])) + ((g0[2][0]+g0[2][2]) + (g0[3][0]+g0[3][2]));
        float e1 = ((g0[0][1]+g0[0][3]) + (g0[1][1]+g0[1][3])) + ((g0[2][1]+g0[2][3]) + (g0[3][1]+g0[3][3]));
        float e2 = ((g1[0][0]+g1[0][2]) + (g1[1][0]+g1[1][2])) + ((g1[2][0]+g1[2][2]) + (g1[3][0]+g1[3][2]));
        float e3 = ((g1[0][1]+g1[0][3]) + (g1[1][1]+g1[1][3])) + ((g1[2][1]+g1[2][3]) + (g1[3][1]+g1[3][3]));
        float s0 = sigmoidf_(e0 + xg0.x);
        float s1 = sigmoidf_(e1 + xg0.y);
        float s2 = sigmoidf_(e2 + xg1.x);
        float s3 = sigmoidf_(e3 + xg1.y);
        if (isR) {
            float2 h01 = *reinterpret_cast<const float2*>(&sH[gid * HS + cA0]);
            float2 h23 = *reinterpret_cast<const float2*>(&sH[gid * HS + cA1]);
            uint32_t lo;
            uint32_t hi = split_pack_h(s0 * h01.x, s1 * h01.y, lo);
            sR[rhOff]     = hi; sR[rhOff + 1] = lo;
            hi = split_pack_h(s2 * h23.x, s3 * h23.y, lo);
            sR[rhOff + 2] = hi; sR[rhOff + 3] = lo;
        } else {
            *reinterpret_cast<float2*>(&sU[gid * HS + cA0 - 128]) = make_float2(s0, s1);
            *reinterpret_cast<float2*>(&sU[gid * HS + cA1 - 128]) = make_float2(s2, s3);
        }
        __syncthreads();

        float2 uu   = *reinterpret_cast<const float2*>(&sU[gid * HS + j0]);
        float2 hold = *reinterpret_cast<const float2*>(&sH[gid * HS + j0]);

        // ---- cand MMA: 4 independent chains of depth 2 ----
        float c[4][4];
        #pragma unroll
        for (int kp = 0; kp < 4; kp++) {
            #pragma unroll
            for (int e = 0; e < 4; e++) c[kp][e] = 0.f;
            uint4 aA = *reinterpret_cast<const uint4*>(&sR[((2*kp)   * 32 + lane) * 4]);
            uint4 aB = *reinterpret_cast<const uint4*>(&sR[((2*kp+1) * 32 + lane) * 4]);
            const uint32_t* pA = reinterpret_cast<const uint32_t*>(&aA);
            const uint32_t* pB = reinterpret_cast<const uint32_t*>(&aB);
            mma16816(c[kp], pA, BcH[2*kp].x,   BcH[2*kp].y);
            mma16816(c[kp], pB, BcH[2*kp+1].x, BcH[2*kp+1].y);
        }

        if (act) {
            float q0 = ((c[0][0]+c[0][2]) + (c[1][0]+c[1][2])) + ((c[2][0]+c[2][2]) + (c[3][0]+c[3][2]));
            float q1 = ((c[0][1]+c[0][3]) + (c[1][1]+c[1][3])) + ((c[2][1]+c[2][3]) + (c[3][1]+c[3][3]));
            float cc0 = tanhf_(q0 + xc.x);
            float cc1 = tanhf_(q1 + xc.y);
            float hn0 = uu.x * hold.x + (1.0f - uu.x) * cc0;
            float hn1 = uu.y * hold.y + (1.0f - uu.y) * cc1;
            *reinterpret_cast<float2*>(&sH[gid * HS + j0]) = make_float2(hn0, hn1);
            uint32_t lo;
            uint32_t hi = split_pack_h(hn0, hn1, lo);
            sA[ahOff]     = hi;
            sA[ahOff + 1] = lo;
        }
        __syncthreads();

        xg0 = xg0n; xg1 = xg1n; xc = xcn;
    }

    float2 hv = *reinterpret_cast<const float2*>(&sH[gid * HS + j0]);
    *reinterpret_cast<float2*>(&out[(size_t)srow[gid] * H_ + j0]) = hv;
}

// ---------------- launch ----------------
extern "C" void kernel_launch(void* const* d_in, const int* in_sizes, int n_in,
                              void* d_out, int out_size) {
    const int*   item_his = (const int*)  d_in[0];
    const int*   seq_lens = (const int*)  d_in[1];
    const float* emb      = (const float*)d_in[2];
    const float* gk       = (const float*)d_in[3];
    const float* gb       = (const float*)d_in[4];
    const float* ck       = (const float*)d_in[5];
    const float* cb       = (const float*)d_in[6];
    float*       out      = (float*)d_out;

    cudaFuncSetAttribute(xproj_mma_kernel, cudaFuncAttributeMaxDynamicSharedMemorySize, PA_SMEM);
    cudaFuncSetAttribute(gru_mma_kernel,   cudaFuncAttributeMaxDynamicSharedMemorySize, G_SMEM);

    setup_kernel<<<2, 256>>>(seq_lens, gk, ck);
    xproj_mma_kernel<<<B_ * 2, 256, PA_SMEM>>>(item_his, seq_lens, emb, gb, cb);
    gru_mma_kernel<<<B_ / 8, 512, G_SMEM>>>(seq_lens, gk, ck, out);
}